// round 1
// baseline (speedup 1.0000x reference)
#include <cuda_runtime.h>
#include <math.h>

#define BSZ   1024
#define NSD   21
#define LL    (BSZ*NSD)      // 21504
#define HD    256            // hidden
#define PHS   25
#define ET    25
#define SEC   (BSZ*PHS*NSD*4) // 2150400 per output section

// ---------------- device scratch (allocation-free) ----------------
__device__ float d_h0[LL*HD];
__device__ float d_h1[LL*HD];
__device__ float d_c0[LL*HD];
__device__ float d_c1[LL*HD];
__device__ float d_gates[LL*1024];
__device__ float d_X[LL*272];
__device__ float d_inp[LL*16];
__device__ float d_kh[LL*ET*8];
__device__ float d_vh[LL*ET*8];
__device__ float d_encz[LL*64];
__device__ float d_ezm[LL*64];
__device__ float d_ym[LL*HD];
__device__ float d_yy[LL*128];
__device__ float d_ymix[LL*128];
__device__ float d_xi[LL*8];
__device__ float d_locst[LL*4];
__device__ float d_Geff[NSD*NSD];
__device__ float d_Wcat[272*1024];
__device__ float d_Wfccat[256*128];
__device__ float d_bcat[128];

// ---------------- helpers ----------------
__device__ __forceinline__ float sigm(float x){ return 1.f/(1.f+expf(-x)); }
__device__ __forceinline__ float wredsum(float v){
    #pragma unroll
    for(int o=16;o;o>>=1) v += __shfl_xor_sync(0xffffffffu, v, o);
    return v;
}
__device__ __forceinline__ float wredmax(float v){
    #pragma unroll
    for(int o=16;o;o>>=1) v = fmaxf(v, __shfl_xor_sync(0xffffffffu, v, o));
    return v;
}

// ---------------- prep kernels ----------------
__global__ void k_prep_geff(const float* __restrict__ G, const float* __restrict__ Ga){
    int t = threadIdx.x;
    if (t < NSD*NSD) d_Geff[t] = G[t] + Ga[t];
}
__global__ void k_prep_wcat(const float* __restrict__ W_ih, const float* __restrict__ W_hh){
    int i = blockIdx.x*blockDim.x + threadIdx.x;
    if (i < 272*1024){
        int r = i >> 10, c = i & 1023;
        d_Wcat[i] = (r < 16) ? W_ih[r*1024 + c] : W_hh[(r-16)*1024 + c];
    }
}
__global__ void k_prep_fc(const float* __restrict__ W_fc, const float* __restrict__ b_fc,
                          const float* __restrict__ W_fc2, const float* __restrict__ b_fc2){
    int i = blockIdx.x*blockDim.x + threadIdx.x;
    if (i < 256*128){
        int r = i >> 7, c = i & 127;
        d_Wfccat[i] = (c < 64) ? W_fc[r*64 + c] : W_fc2[r*64 + (c-64)];
    }
    if (i < 128) d_bcat[i] = (i < 64) ? b_fc[i] : b_fc2[i-64];
}
__global__ void k_encz(const float* __restrict__ z, const float* __restrict__ enc){
    int idx = blockIdx.x*blockDim.x + threadIdx.x;
    if (idx < LL*64){
        int l = idx >> 6, c = idx & 63;
        d_encz[idx] = (c < 32) ? z[l*32 + c] : enc[l*32 + (c-32)];
    }
}
__global__ void k_kv(const float* __restrict__ fe, const float* __restrict__ Wk,
                     const float* __restrict__ bk, const float* __restrict__ Wv,
                     const float* __restrict__ bv){
    int idx = blockIdx.x*blockDim.x + threadIdx.x;
    if (idx >= LL*ET) return;
    int l = idx / ET, t = idx - l*ET;
    int b = l / NSD, n = l - b*NSD;
    const float* s = fe + (((size_t)b*ET + t)*NSD + n)*8;
    float v[8];
    #pragma unroll
    for(int i=0;i<8;i++) v[i] = s[i];
    #pragma unroll
    for(int j=0;j<8;j++){
        float ka = bk[j], va = bv[j];
        #pragma unroll
        for(int i=0;i<8;i++){ ka += v[i]*Wk[i*8+j]; va += v[i]*Wv[i*8+j]; }
        d_kh[(size_t)idx*8 + j] = ka;
        d_vh[(size_t)idx*8 + j] = va;
    }
}
__global__ void k_init(const float* __restrict__ x){
    int idx = blockIdx.x*blockDim.x + threadIdx.x;
    if (idx < LL*8){
        d_xi[idx] = x[idx];
        int j = idx & 7;
        if (j < 4) d_locst[(idx>>3)*4 + j] = x[idx];
    }
}

// ---------------- G-mix: out[b,n,col] = sum_m G[n,m] * (relu?)in[b,m,col] ----------------
__global__ void k_mix(const float* __restrict__ Gm, const float* __restrict__ in, int cols,
                      float* __restrict__ out, int ostride, int ooff, int relu_in){
    __shared__ float Gs[NSD*NSD];
    for (int i = threadIdx.x; i < NSD*NSD; i += blockDim.x) Gs[i] = Gm[i];
    __syncthreads();
    int gid = blockIdx.x*blockDim.x + threadIdx.x;
    if (gid >= BSZ*cols) return;
    int b = gid / cols, col = gid - b*cols;
    const float* base = in + (size_t)b*NSD*cols + col;
    float v[NSD];
    #pragma unroll
    for (int m=0;m<NSD;m++){
        float t = base[(size_t)m*cols];
        v[m] = relu_in ? fmaxf(t, 0.f) : t;
    }
    float* ob = out + (size_t)b*NSD*ostride + ooff + col;
    #pragma unroll
    for (int n=0;n<NSD;n++){
        float a = 0.f;
        #pragma unroll
        for (int m=0;m<NSD;m++) a += Gs[n*NSD+m]*v[m];
        ob[(size_t)n*ostride] = a;
    }
}

// ---------------- tiled fp32 GEMM: C = A(MxK) @ B(KxN) + bias, optional relu ----------------
// M % 128 == 0, N % 128 == 0, K % 8 == 0 (all guaranteed here)
__global__ void __launch_bounds__(256,2) k_gemm(const float* __restrict__ A,
                                                const float* __restrict__ B,
                                                const float* __restrict__ bias,
                                                float* __restrict__ C,
                                                int M, int N, int K, int relu){
    __shared__ __align__(16) float As[2][8][132];
    __shared__ __align__(16) float Bs[2][8][128];
    int tid  = threadIdx.x;
    int row0 = blockIdx.y * 128;
    int col0 = blockIdx.x * 128;
    int ar = tid >> 1, ak = (tid & 1) * 4;
    int bk = tid >> 5, bc = (tid & 31) * 4;
    const float* Aptr = A + (size_t)(row0 + ar)*K + ak;
    const float* Bptr = B + (size_t)bk*N + col0 + bc;
    int nIter = K >> 3;

    float4 a4 = *(const float4*)Aptr;
    float4 b4 = *(const float4*)Bptr;
    As[0][ak+0][ar]=a4.x; As[0][ak+1][ar]=a4.y; As[0][ak+2][ar]=a4.z; As[0][ak+3][ar]=a4.w;
    *(float4*)&Bs[0][bk][bc] = b4;
    __syncthreads();

    float acc[8][8];
    #pragma unroll
    for(int i=0;i<8;i++)
        #pragma unroll
        for(int j=0;j<8;j++) acc[i][j]=0.f;

    int ty = tid >> 4, tx = tid & 15;
    for (int it = 0; it < nIter; ++it){
        int buf = it & 1;
        if (it+1 < nIter){
            a4 = *(const float4*)(Aptr + (size_t)(it+1)*8);
            b4 = *(const float4*)(Bptr + (size_t)(it+1)*8*N);
        }
        #pragma unroll
        for (int kk=0;kk<8;kk++){
            float4 af0 = *(const float4*)&As[buf][kk][ty*8];
            float4 af1 = *(const float4*)&As[buf][kk][ty*8+4];
            float4 bf0 = *(const float4*)&Bs[buf][kk][tx*8];
            float4 bf1 = *(const float4*)&Bs[buf][kk][tx*8+4];
            float af[8] = {af0.x,af0.y,af0.z,af0.w,af1.x,af1.y,af1.z,af1.w};
            float bf[8] = {bf0.x,bf0.y,bf0.z,bf0.w,bf1.x,bf1.y,bf1.z,bf1.w};
            #pragma unroll
            for(int i=0;i<8;i++)
                #pragma unroll
                for(int j=0;j<8;j++) acc[i][j] += af[i]*bf[j];
        }
        __syncthreads();
        if (it+1 < nIter){
            int nb = buf ^ 1;
            As[nb][ak+0][ar]=a4.x; As[nb][ak+1][ar]=a4.y; As[nb][ak+2][ar]=a4.z; As[nb][ak+3][ar]=a4.w;
            *(float4*)&Bs[nb][bk][bc] = b4;
            __syncthreads();
        }
    }
    #pragma unroll
    for(int i=0;i<8;i++){
        int r = row0 + ty*8 + i;
        float* Crow = C + (size_t)r*N + col0 + tx*8;
        #pragma unroll
        for(int j=0;j<8;j++){
            float v = acc[i][j] + bias[col0 + tx*8 + j];
            if (relu) v = fmaxf(v, 0.f);
            Crow[j] = v;
        }
    }
}

// ---------------- attention (warp per row): builds inp = [xi | q+o] ----------------
__global__ void __launch_bounds__(128) k_attn(const float* __restrict__ c,
                                              const float* __restrict__ Whd, const float* __restrict__ bhd,
                                              const float* __restrict__ Wq,  const float* __restrict__ bq,
                                              const float* __restrict__ Wo,  const float* __restrict__ bo){
    __shared__ float sWhd[2048];
    __shared__ float sWq[64], sWo[64], sbhd[8], sbq[8], sbo[8];
    int tid = threadIdx.x;
    for (int i = tid; i < 2048; i += 128) sWhd[i] = Whd[i];
    if (tid < 64){ sWq[tid] = Wq[tid]; sWo[tid] = Wo[tid]; }
    if (tid < 8){ sbhd[tid]=bhd[tid]; sbq[tid]=bq[tid]; sbo[tid]=bo[tid]; }
    __syncthreads();

    int l = blockIdx.x*4 + (tid >> 5);
    int lane = tid & 31;
    const float* crow = c + (size_t)l*HD;

    // q = c @ W_hd + b_hd
    float acc[8] = {0,0,0,0,0,0,0,0};
    #pragma unroll
    for (int kk=0;kk<8;kk++){
        int k = lane + kk*32;
        float cv = crow[k];
        #pragma unroll
        for(int j=0;j<8;j++) acc[j] += cv * sWhd[k*8+j];
    }
    float q[8];
    #pragma unroll
    for(int j=0;j<8;j++) q[j] = wredsum(acc[j]) + sbhd[j];

    // qh = q @ Wq + bq (redundant per lane)
    float qh[8];
    #pragma unroll
    for(int j=0;j<8;j++){
        float s = sbq[j];
        #pragma unroll
        for(int i=0;i<8;i++) s += q[i]*sWq[i*8+j];
        qh[j] = s;
    }

    const float* khr = d_kh + (size_t)l*ET*8;
    const float* vhr = d_vh + (size_t)l*ET*8;
    float o8[8];
    #pragma unroll
    for (int h=0; h<2; h++){
        float logit = -1e30f;
        if (lane < ET){
            float s = 0.f;
            #pragma unroll
            for(int d=0;d<4;d++) s += qh[h*4+d]*khr[lane*8 + h*4 + d];
            logit = s*0.5f;  // scale = 1/sqrt(HD=4)
        }
        float mx = wredmax(logit);
        float e  = (lane < ET) ? expf(logit - mx) : 0.f;
        float sm = wredsum(e);
        float w  = e / sm;
        float od[4] = {0,0,0,0};
        if (lane < ET){
            #pragma unroll
            for(int d=0;d<4;d++) od[d] = w * vhr[lane*8 + h*4 + d];
        }
        #pragma unroll
        for(int d=0;d<4;d++) o8[h*4+d] = wredsum(od[d]);
    }

    if (lane < 16){
        float outv;
        if (lane < 8){
            outv = d_xi[(size_t)l*8 + lane];
        } else {
            int j = lane - 8;
            float s = sbo[j] + q[j];
            #pragma unroll
            for(int i=0;i<8;i++) s += o8[i]*sWo[i*8+j];
            outv = s;
        }
        d_inp[(size_t)l*16 + lane] = outv;
    }
}

// ---------------- LSTM pointwise ----------------
__global__ void k_lstm(const float* __restrict__ cin, float* __restrict__ cout,
                       float* __restrict__ hout){
    int idx = blockIdx.x*blockDim.x + threadIdx.x;
    if (idx >= LL*HD) return;
    int l = idx >> 8, j = idx & 255;
    const float* g = d_gates + (size_t)l*1024;
    float ig = sigm(g[j]);
    float fg = sigm(g[256+j]);
    float gg = tanhf(g[512+j]);
    float og = sigm(g[768+j]);
    float c2 = fg*cin[idx] + ig*gg;
    cout[idx] = c2;
    hout[idx] = og*tanhf(c2);
}

// ---------------- final heads + quaternion (warp per row) ----------------
__global__ void __launch_bounds__(128) k_final(const float* __restrict__ Wloc, const float* __restrict__ bloc,
                                               const float* __restrict__ Wlz,  const float* __restrict__ blz,
                                               float* __restrict__ out, int s){
    __shared__ float sWl[192], sWz[256], sbl[3], sbz[4];
    int tid = threadIdx.x;
    for (int i=tid;i<192;i+=128) sWl[i]=Wloc[i];
    for (int i=tid;i<256;i+=128) sWz[i]=Wlz[i];
    if (tid<3) sbl[tid]=bloc[tid];
    if (tid<4) sbz[tid]=blz[tid];
    __syncthreads();

    int l = blockIdx.x*4 + (tid >> 5);
    int lane = tid & 31;
    const float* yr = d_ymix + (size_t)l*128;

    float p0=0,p1=0,p2=0, z0=0,z1=0,z2=0,z3=0;
    #pragma unroll
    for (int kk=0;kk<2;kk++){
        int k = lane + kk*32;
        float y1 = yr[k];
        p0 += y1*sWl[k*3+0]; p1 += y1*sWl[k*3+1]; p2 += y1*sWl[k*3+2];
        float y2 = yr[64+k];
        z0 += y2*sWz[k*4+0]; z1 += y2*sWz[k*4+1]; z2 += y2*sWz[k*4+2]; z3 += y2*sWz[k*4+3];
    }
    p0=wredsum(p0); p1=wredsum(p1); p2=wredsum(p2);
    z0=wredsum(z0); z1=wredsum(z1); z2=wredsum(z2); z3=wredsum(z3);

    float l0=p0+sbl[0], l1=p1+sbl[1], l2=p2+sbl[2];
    float lz0=(z0+sbz[0])*100.f, lz1=(z1+sbz[1])*100.f, lz2=(z2+sbz[2])*100.f, lz3=(z3+sbz[3])*100.f;

    float inv = 1.f / sqrtf(1.f + l0*l0 + l1*l1 + l2*l2);
    float dw = inv, dx = l0*inv, dy = l1*inv, dz = l2*inv;

    float s0 = d_locst[(size_t)l*4+0], s1 = d_locst[(size_t)l*4+1];
    float s2 = d_locst[(size_t)l*4+2], s3 = d_locst[(size_t)l*4+3];

    float w  = s0*dw - (s1*dx + s2*dy + s3*dz);
    float vx = s0*dx + dw*s1 + (s2*dz - s3*dy);
    float vy = s0*dy + dw*s2 + (s3*dx - s1*dz);
    float vz = s0*dz + dw*s3 + (s1*dy - s2*dx);

    int b = l / NSD, n = l - b*NSD;
    size_t base = (((size_t)b*PHS + s)*NSD + n)*4;
    if (lane < 4){
        float lv = (lane==0)?w  : (lane==1)?vx : (lane==2)?vy : vz;
        float dv = (lane==0)?dw : (lane==1)?dx : (lane==2)?dy : dz;
        float zv = (lane==0)?lz0: (lane==1)?lz1: (lane==2)?lz2: lz3;
        out[base + lane]          = lv;
        out[SEC + base + lane]    = dv;
        out[2*(size_t)SEC + base + lane] = zv;
        d_locst[(size_t)l*4 + lane] = lv;
        d_xi[(size_t)l*8 + lane]     = lv;
        d_xi[(size_t)l*8 + 4 + lane] = dv;
    }
}

// ---------------- host ----------------
extern "C" void kernel_launch(void* const* d_in, const int* in_sizes, int n_in,
                              void* d_out, int out_size){
    const float* x      = (const float*)d_in[0];
    const float* enc    = (const float*)d_in[1];
    const float* fe     = (const float*)d_in[2];
    const float* z      = (const float*)d_in[3];
    // d_in[4] = y (unused)
    const float* G      = (const float*)d_in[5];
    const float* Gadd   = (const float*)d_in[6];
    const float* W_ih   = (const float*)d_in[7];
    const float* W_hh   = (const float*)d_in[8];
    const float* b_lstm = (const float*)d_in[9];
    const float* W_fc   = (const float*)d_in[10];
    const float* b_fc   = (const float*)d_in[11];
    const float* W_fc2  = (const float*)d_in[12];
    const float* b_fc2  = (const float*)d_in[13];
    const float* W_h1   = (const float*)d_in[14];
    const float* b_h1   = (const float*)d_in[15];
    const float* W_h2   = (const float*)d_in[16];
    const float* b_h2   = (const float*)d_in[17];
    const float* W_hd   = (const float*)d_in[18];
    const float* b_hd   = (const float*)d_in[19];
    const float* Wq     = (const float*)d_in[20];
    const float* bq     = (const float*)d_in[21];
    const float* Wk     = (const float*)d_in[22];
    const float* bk     = (const float*)d_in[23];
    const float* Wv     = (const float*)d_in[24];
    const float* bv     = (const float*)d_in[25];
    const float* Wo     = (const float*)d_in[26];
    const float* bo     = (const float*)d_in[27];
    const float* W_loc  = (const float*)d_in[28];
    const float* b_loc  = (const float*)d_in[29];
    const float* W_lz   = (const float*)d_in[30];
    const float* b_lz   = (const float*)d_in[31];
    float* out = (float*)d_out;

    float *ph0,*ph1,*pc0,*pc1,*pgeff,*pencz,*pezm,*pX,*pinp,*pym,*pyy,*pymix,*pgates,*pwcat,*pwfc,*pbcat;
    cudaGetSymbolAddress((void**)&ph0,   d_h0);
    cudaGetSymbolAddress((void**)&ph1,   d_h1);
    cudaGetSymbolAddress((void**)&pc0,   d_c0);
    cudaGetSymbolAddress((void**)&pc1,   d_c1);
    cudaGetSymbolAddress((void**)&pgeff, d_Geff);
    cudaGetSymbolAddress((void**)&pencz, d_encz);
    cudaGetSymbolAddress((void**)&pezm,  d_ezm);
    cudaGetSymbolAddress((void**)&pX,    d_X);
    cudaGetSymbolAddress((void**)&pinp,  d_inp);
    cudaGetSymbolAddress((void**)&pym,   d_ym);
    cudaGetSymbolAddress((void**)&pyy,   d_yy);
    cudaGetSymbolAddress((void**)&pymix, d_ymix);
    cudaGetSymbolAddress((void**)&pgates,d_gates);
    cudaGetSymbolAddress((void**)&pwcat, d_Wcat);
    cudaGetSymbolAddress((void**)&pwfc,  d_Wfccat);
    cudaGetSymbolAddress((void**)&pbcat, d_bcat);

    // prologue
    k_prep_geff<<<1, 512>>>(G, Gadd);
    k_prep_wcat<<<(272*1024 + 255)/256, 256>>>(W_ih, W_hh);
    k_prep_fc<<<(256*128 + 255)/256, 256>>>(W_fc, b_fc, W_fc2, b_fc2);
    k_encz<<<(LL*64 + 255)/256, 256>>>(z, enc);
    k_mix<<<(BSZ*64 + 127)/128, 128>>>(G, pencz, 64, pezm, 64, 0, 0);
    k_gemm<<<dim3(2,168), 256>>>(pezm, W_h1, b_h1, ph0, LL, 256, 64, 0);
    k_gemm<<<dim3(2,168), 256>>>(pezm, W_h2, b_h2, pc0, LL, 256, 64, 0);
    k_kv<<<(LL*ET + 127)/128, 128>>>(fe, Wk, bk, Wv, bv);
    k_init<<<(LL*8 + 255)/256, 256>>>(x);

    for (int s = 0; s < PHS; ++s){
        float* hc = (s & 1) ? ph1 : ph0;
        float* cc = (s & 1) ? pc1 : pc0;
        float* hn = (s & 1) ? ph0 : ph1;
        float* cn = (s & 1) ? pc0 : pc1;

        k_attn<<<LL/4, 128>>>(cc, W_hd, b_hd, Wq, bq, Wo, bo);
        k_mix<<<(BSZ*16  + 127)/128, 128>>>(pgeff, pinp, 16,  pX, 272, 0,  0);
        k_mix<<<(BSZ*256 + 127)/128, 128>>>(pgeff, hc,   256, pX, 272, 16, 0);
        k_gemm<<<dim3(8,168), 256>>>(pX, pwcat, b_lstm, pgates, LL, 1024, 272, 0);
        k_lstm<<<(LL*256 + 255)/256, 256>>>(cc, cn, hn);
        k_mix<<<(BSZ*256 + 127)/128, 128>>>(G, hn, 256, pym, 256, 0, 1);
        k_gemm<<<dim3(1,168), 256>>>(pym, pwfc, pbcat, pyy, LL, 128, 256, 1);
        k_mix<<<(BSZ*128 + 127)/128, 128>>>(G, pyy, 128, pymix, 128, 0, 0);
        k_final<<<LL/4, 128>>>(W_loc, b_loc, W_lz, b_lz, out, s);
    }
}

// round 6
// speedup vs baseline: 2.0985x; 2.0985x over previous
#include <cuda_runtime.h>
#include <stdint.h>
#include <math.h>

#define BSZ   1024
#define NSD   21
#define LL    (BSZ*NSD)      // 21504
#define HD    256            // hidden
#define PHS   25
#define ET    25
#define SEC   (BSZ*PHS*NSD*4) // 2150400 per output section

// ---------------- device scratch (allocation-free) ----------------
__device__ float d_h0[LL*HD];
__device__ float d_h1[LL*HD];
__device__ float d_c0[LL*HD];
__device__ float d_c1[LL*HD];
__device__ float d_X[LL*272];
__device__ float d_inp[LL*16];
__device__ float d_kh[LL*ET*8];
__device__ float d_vh[LL*ET*8];
__device__ float d_encz[LL*64];
__device__ float d_ezm[LL*64];
__device__ float d_ym[LL*HD];
__device__ float d_yy[LL*128];
__device__ float d_ymix[LL*128];
__device__ float d_xi[LL*8];
__device__ float d_locst[LL*4];
__device__ float d_Geff[NSD*NSD];
__device__ float d_Wcat[272*1024];   // column-PERMUTED for fused LSTM epilogue
__device__ float d_Wfccat[256*128];
__device__ float d_bcat[128];

// ---------------- helpers ----------------
__device__ __forceinline__ float sigm(float x){ return 1.f/(1.f+expf(-x)); }
__device__ __forceinline__ float wredsum(float v){
    #pragma unroll
    for(int o=16;o;o>>=1) v += __shfl_xor_sync(0xffffffffu, v, o);
    return v;
}
__device__ __forceinline__ float wredmax(float v){
    #pragma unroll
    for(int o=16;o;o>>=1) v = fmaxf(v, __shfl_xor_sync(0xffffffffu, v, o));
    return v;
}
__device__ __forceinline__ unsigned int f2tf(float f){
    unsigned int r; asm("cvt.rna.tf32.f32 %0, %1;" : "=r"(r) : "f"(f)); return r;
}
__device__ __forceinline__ void mma_tf32(float c[4], const unsigned int a[4], const unsigned int b[2]){
    asm volatile(
        "mma.sync.aligned.m16n8k8.row.col.f32.tf32.tf32.f32 "
        "{%0,%1,%2,%3}, {%4,%5,%6,%7}, {%8,%9}, {%0,%1,%2,%3};"
        : "+f"(c[0]), "+f"(c[1]), "+f"(c[2]), "+f"(c[3])
        : "r"(a[0]), "r"(a[1]), "r"(a[2]), "r"(a[3]), "r"(b[0]), "r"(b[1]));
}

// ---------------- prep kernels ----------------
__global__ void k_prep_geff(const float* __restrict__ G, const float* __restrict__ Ga){
    int t = threadIdx.x;
    if (t < NSD*NSD) d_Geff[t] = G[t] + Ga[t];
}
// permute columns: phys col p holds logical col  gate*256 + (p/32)*8 + (p%8), gate=(p%32)/8
__global__ void k_prep_wcat(const float* __restrict__ W_ih, const float* __restrict__ W_hh){
    int i = blockIdx.x*blockDim.x + threadIdx.x;
    if (i < 272*1024){
        int r = i >> 10, p = i & 1023;
        int ws = p >> 5, s = p & 31;
        int gate = s >> 3, jj = s & 7;
        int lc = gate*256 + ws*8 + jj;
        d_Wcat[i] = (r < 16) ? W_ih[r*1024 + lc] : W_hh[(r-16)*1024 + lc];
    }
}
__global__ void k_prep_fc(const float* __restrict__ W_fc, const float* __restrict__ b_fc,
                          const float* __restrict__ W_fc2, const float* __restrict__ b_fc2){
    int i = blockIdx.x*blockDim.x + threadIdx.x;
    if (i < 256*128){
        int r = i >> 7, c = i & 127;
        d_Wfccat[i] = (c < 64) ? W_fc[r*64 + c] : W_fc2[r*64 + (c-64)];
    }
    if (i < 128) d_bcat[i] = (i < 64) ? b_fc[i] : b_fc2[i-64];
}
__global__ void k_encz(const float* __restrict__ z, const float* __restrict__ enc){
    int idx = blockIdx.x*blockDim.x + threadIdx.x;
    if (idx < LL*64){
        int l = idx >> 6, c = idx & 63;
        d_encz[idx] = (c < 32) ? z[l*32 + c] : enc[l*32 + (c-32)];
    }
}
__global__ void k_kv(const float* __restrict__ fe, const float* __restrict__ Wk,
                     const float* __restrict__ bk, const float* __restrict__ Wv,
                     const float* __restrict__ bv){
    int idx = blockIdx.x*blockDim.x + threadIdx.x;
    if (idx >= LL*ET) return;
    int l = idx / ET, t = idx - l*ET;
    int b = l / NSD, n = l - b*NSD;
    const float* s = fe + (((size_t)b*ET + t)*NSD + n)*8;
    float v[8];
    #pragma unroll
    for(int i=0;i<8;i++) v[i] = s[i];
    #pragma unroll
    for(int j=0;j<8;j++){
        float ka = bk[j], va = bv[j];
        #pragma unroll
        for(int i=0;i<8;i++){ ka += v[i]*Wk[i*8+j]; va += v[i]*Wv[i*8+j]; }
        d_kh[(size_t)idx*8 + j] = ka;
        d_vh[(size_t)idx*8 + j] = va;
    }
}
__global__ void k_init(const float* __restrict__ x){
    int idx = blockIdx.x*blockDim.x + threadIdx.x;
    if (idx < LL*8){
        d_xi[idx] = x[idx];
        int j = idx & 7;
        if (j < 4) d_locst[(idx>>3)*4 + j] = x[idx];
    }
}

// ---------------- G-mix: out[b,n,col] = sum_m G[n,m] * (relu?)in[b,m,col] ----------------
__global__ void k_mix(const float* __restrict__ Gm, const float* __restrict__ in, int cols,
                      float* __restrict__ out, int ostride, int ooff, int relu_in){
    __shared__ float Gs[NSD*NSD];
    for (int i = threadIdx.x; i < NSD*NSD; i += blockDim.x) Gs[i] = Gm[i];
    __syncthreads();
    int gid = blockIdx.x*blockDim.x + threadIdx.x;
    if (gid >= BSZ*cols) return;
    int b = gid / cols, col = gid - b*cols;
    const float* base = in + (size_t)b*NSD*cols + col;
    float v[NSD];
    #pragma unroll
    for (int m=0;m<NSD;m++){
        float t = base[(size_t)m*cols];
        v[m] = relu_in ? fmaxf(t, 0.f) : t;
    }
    float* ob = out + (size_t)b*NSD*ostride + ooff + col;
    #pragma unroll
    for (int n=0;n<NSD;n++){
        float a = 0.f;
        #pragma unroll
        for (int m=0;m<NSD;m++) a += Gs[n*NSD+m]*v[m];
        ob[(size_t)n*ostride] = a;
    }
}

// =====================================================================
// tf32 tensor-core GEMM skeleton.
// Block tile 128x128, 256 threads (8 warps: 2x4), warp tile 64x32.
// Per k-panel of 8: As[8][136] (k x row, tf32 bits), Bs[8][136] (k x col).
// =====================================================================
#define GEMM_PROLOG(Aptr, Bptr, Kc, Nc)                                       \
    __shared__ unsigned int As[2][8][136];                                    \
    __shared__ unsigned int Bs[2][8][136];                                    \
    int tid  = threadIdx.x;                                                   \
    int lane = tid & 31, w = tid >> 5;                                        \
    int warp_m0 = (w >> 2) * 64, warp_n0 = (w & 3) * 32;                      \
    int g = lane >> 2, tg = lane & 3;                                         \
    int row0 = blockIdx.y * 128;                                              \
    int col0 = blockIdx.x * 128;                                              \
    int arow = tid >> 1, akk = (tid & 1) * 4;                                 \
    int brow = tid >> 5, bcc = (tid & 31) * 4;                                \
    const float* Ag = (Aptr) + (size_t)(row0 + arow)*(Kc) + akk;              \
    const float* Bg = (Bptr) + (size_t)brow*(Nc) + col0 + bcc;                \
    int KP = (Kc) >> 3;                                                       \
    float acc[4][4][4];                                                       \
    _Pragma("unroll")                                                         \
    for (int i=0;i<4;i++) _Pragma("unroll") for(int j=0;j<4;j++)              \
        _Pragma("unroll") for(int k=0;k<4;k++) acc[i][j][k]=0.f;              \
    float4 a4 = *(const float4*)Ag;                                           \
    float4 b4 = *(const float4*)Bg;                                           \
    As[0][akk+0][arow]=f2tf(a4.x); As[0][akk+1][arow]=f2tf(a4.y);             \
    As[0][akk+2][arow]=f2tf(a4.z); As[0][akk+3][arow]=f2tf(a4.w);             \
    Bs[0][brow][bcc+0]=f2tf(b4.x); Bs[0][brow][bcc+1]=f2tf(b4.y);             \
    Bs[0][brow][bcc+2]=f2tf(b4.z); Bs[0][brow][bcc+3]=f2tf(b4.w);             \
    __syncthreads();                                                          \
    for (int kp = 0; kp < KP; ++kp){                                          \
        int buf = kp & 1;                                                     \
        if (kp+1 < KP){                                                       \
            a4 = *(const float4*)(Ag + (size_t)(kp+1)*8);                     \
            b4 = *(const float4*)(Bg + (size_t)(kp+1)*8*(Nc));                \
        }                                                                     \
        unsigned int ar[4][4], br[4][2];                                      \
        _Pragma("unroll")                                                     \
        for (int mi=0; mi<4; mi++){                                           \
            int r0 = warp_m0 + mi*16 + g;                                     \
            ar[mi][0] = As[buf][tg  ][r0];                                    \
            ar[mi][1] = As[buf][tg  ][r0+8];                                  \
            ar[mi][2] = As[buf][tg+4][r0];                                    \
            ar[mi][3] = As[buf][tg+4][r0+8];                                  \
        }                                                                     \
        _Pragma("unroll")                                                     \
        for (int ni=0; ni<4; ni++){                                           \
            int n0 = warp_n0 + ni*8 + g;                                      \
            br[ni][0] = Bs[buf][tg  ][n0];                                    \
            br[ni][1] = Bs[buf][tg+4][n0];                                    \
        }                                                                     \
        _Pragma("unroll")                                                     \
        for (int mi=0; mi<4; mi++)                                            \
            _Pragma("unroll")                                                 \
            for (int ni=0; ni<4; ni++)                                        \
                mma_tf32(acc[mi][ni], ar[mi], br[ni]);                        \
        if (kp+1 < KP){                                                       \
            int nb = buf ^ 1;                                                 \
            As[nb][akk+0][arow]=f2tf(a4.x); As[nb][akk+1][arow]=f2tf(a4.y);   \
            As[nb][akk+2][arow]=f2tf(a4.z); As[nb][akk+3][arow]=f2tf(a4.w);   \
            Bs[nb][brow][bcc+0]=f2tf(b4.x); Bs[nb][brow][bcc+1]=f2tf(b4.y);   \
            Bs[nb][brow][bcc+2]=f2tf(b4.z); Bs[nb][brow][bcc+3]=f2tf(b4.w);   \
            __syncthreads();                                                  \
        }                                                                     \
    }

// ---------- generic tf32 GEMM: C = A@B + bias, optional relu ----------
__global__ void __launch_bounds__(256) k_gemm_tf32(const float* __restrict__ A,
                                                   const float* __restrict__ B,
                                                   const float* __restrict__ bias,
                                                   float* __restrict__ C,
                                                   int N, int K, int relu){
    GEMM_PROLOG(A, B, K, N)
    #pragma unroll
    for (int mi=0; mi<4; mi++){
        #pragma unroll
        for (int ni=0; ni<4; ni++){
            int r  = row0 + warp_m0 + mi*16 + g;
            int cb = col0 + warp_n0 + ni*8 + 2*tg;
            float b0v = bias[cb], b1v = bias[cb+1];
            float v0 = acc[mi][ni][0]+b0v, v1 = acc[mi][ni][1]+b1v;
            float v2 = acc[mi][ni][2]+b0v, v3 = acc[mi][ni][3]+b1v;
            if (relu){ v0=fmaxf(v0,0.f); v1=fmaxf(v1,0.f); v2=fmaxf(v2,0.f); v3=fmaxf(v3,0.f); }
            *(float2*)(C + (size_t)r*N + cb)     = make_float2(v0, v1);
            *(float2*)(C + (size_t)(r+8)*N + cb) = make_float2(v2, v3);
        }
    }
}

// ---------- LSTM-fused tf32 GEMM: gates = X@WcatPerm + b; then LSTM pointwise ----------
// N=1024 (permuted), K=272.  ni index == gate (0=i,1=f,2=g,3=o).
__global__ void __launch_bounds__(256) k_gemm_lstm(const float* __restrict__ A,
                                                   const float* __restrict__ B,
                                                   const float* __restrict__ bias,
                                                   const float* __restrict__ cin,
                                                   float* __restrict__ cout,
                                                   float* __restrict__ hout){
    GEMM_PROLOG(A, B, 272, 1024)
    int ws = (col0 + warp_n0) >> 5;       // 0..31
    int j0 = ws*8 + 2*tg;                 // hidden-unit index for cp=0
    float bI[2] = { bias[      j0], bias[      j0+1] };
    float bF[2] = { bias[256 + j0], bias[256 + j0+1] };
    float bG[2] = { bias[512 + j0], bias[512 + j0+1] };
    float bO[2] = { bias[768 + j0], bias[768 + j0+1] };
    #pragma unroll
    for (int mi=0; mi<4; mi++){
        #pragma unroll
        for (int rh=0; rh<2; rh++){
            int r = row0 + warp_m0 + mi*16 + g + rh*8;
            #pragma unroll
            for (int cp=0; cp<2; cp++){
                int fi = rh*2 + cp;
                int j  = j0 + cp;
                float iv = sigm (acc[mi][0][fi] + bI[cp]);
                float fv = sigm (acc[mi][1][fi] + bF[cp]);
                float gv = tanhf(acc[mi][2][fi] + bG[cp]);
                float ov = sigm (acc[mi][3][fi] + bO[cp]);
                float c2 = fv * cin[(size_t)r*256 + j] + iv*gv;
                cout[(size_t)r*256 + j] = c2;
                hout[(size_t)r*256 + j] = ov * tanhf(c2);
            }
        }
    }
}

// ---------------- attention (warp per row): builds inp = [xi | q+o] ----------------
__global__ void __launch_bounds__(128) k_attn(const float* __restrict__ c,
                                              const float* __restrict__ Whd, const float* __restrict__ bhd,
                                              const float* __restrict__ Wq,  const float* __restrict__ bq,
                                              const float* __restrict__ Wo,  const float* __restrict__ bo){
    __shared__ float sWhd[2048];
    __shared__ float sWq[64], sWo[64], sbhd[8], sbq[8], sbo[8];
    int tid = threadIdx.x;
    for (int i = tid; i < 2048; i += 128) sWhd[i] = Whd[i];
    if (tid < 64){ sWq[tid] = Wq[tid]; sWo[tid] = Wo[tid]; }
    if (tid < 8){ sbhd[tid]=bhd[tid]; sbq[tid]=bq[tid]; sbo[tid]=bo[tid]; }
    __syncthreads();

    int l = blockIdx.x*4 + (tid >> 5);
    int lane = tid & 31;
    const float* crow = c + (size_t)l*HD;

    float acc[8] = {0,0,0,0,0,0,0,0};
    #pragma unroll
    for (int kk=0;kk<8;kk++){
        int k = lane + kk*32;
        float cv = crow[k];
        #pragma unroll
        for(int j=0;j<8;j++) acc[j] += cv * sWhd[k*8+j];
    }
    float q[8];
    #pragma unroll
    for(int j=0;j<8;j++) q[j] = wredsum(acc[j]) + sbhd[j];

    float qh[8];
    #pragma unroll
    for(int j=0;j<8;j++){
        float s = sbq[j];
        #pragma unroll
        for(int i=0;i<8;i++) s += q[i]*sWq[i*8+j];
        qh[j] = s;
    }

    const float* khr = d_kh + (size_t)l*ET*8;
    const float* vhr = d_vh + (size_t)l*ET*8;
    float o8[8];
    #pragma unroll
    for (int h=0; h<2; h++){
        float logit = -1e30f;
        if (lane < ET){
            float s = 0.f;
            #pragma unroll
            for(int d=0;d<4;d++) s += qh[h*4+d]*khr[lane*8 + h*4 + d];
            logit = s*0.5f;
        }
        float mx = wredmax(logit);
        float e  = (lane < ET) ? expf(logit - mx) : 0.f;
        float sm = wredsum(e);
        float wgt= e / sm;
        float od[4] = {0,0,0,0};
        if (lane < ET){
            #pragma unroll
            for(int d=0;d<4;d++) od[d] = wgt * vhr[lane*8 + h*4 + d];
        }
        #pragma unroll
        for(int d=0;d<4;d++) o8[h*4+d] = wredsum(od[d]);
    }

    if (lane < 16){
        float outv;
        if (lane < 8){
            outv = d_xi[(size_t)l*8 + lane];
        } else {
            int j = lane - 8;
            float s = sbo[j] + q[j];
            #pragma unroll
            for(int i=0;i<8;i++) s += o8[i]*sWo[i*8+j];
            outv = s;
        }
        d_inp[(size_t)l*16 + lane] = outv;
    }
}

// ---------------- final heads + quaternion (warp per row) ----------------
__global__ void __launch_bounds__(128) k_final(const float* __restrict__ Wloc, const float* __restrict__ bloc,
                                               const float* __restrict__ Wlz,  const float* __restrict__ blz,
                                               float* __restrict__ out, int s){
    __shared__ float sWl[192], sWz[256], sbl[3], sbz[4];
    int tid = threadIdx.x;
    for (int i=tid;i<192;i+=128) sWl[i]=Wloc[i];
    for (int i=tid;i<256;i+=128) sWz[i]=Wlz[i];
    if (tid<3) sbl[tid]=bloc[tid];
    if (tid<4) sbz[tid]=blz[tid];
    __syncthreads();

    int l = blockIdx.x*4 + (tid >> 5);
    int lane = tid & 31;
    const float* yr = d_ymix + (size_t)l*128;

    float p0=0,p1=0,p2=0, z0=0,z1=0,z2=0,z3=0;
    #pragma unroll
    for (int kk=0;kk<2;kk++){
        int k = lane + kk*32;
        float y1 = yr[k];
        p0 += y1*sWl[k*3+0]; p1 += y1*sWl[k*3+1]; p2 += y1*sWl[k*3+2];
        float y2 = yr[64+k];
        z0 += y2*sWz[k*4+0]; z1 += y2*sWz[k*4+1]; z2 += y2*sWz[k*4+2]; z3 += y2*sWz[k*4+3];
    }
    p0=wredsum(p0); p1=wredsum(p1); p2=wredsum(p2);
    z0=wredsum(z0); z1=wredsum(z1); z2=wredsum(z2); z3=wredsum(z3);

    float l0=p0+sbl[0], l1=p1+sbl[1], l2=p2+sbl[2];
    float lz0=(z0+sbz[0])*100.f, lz1=(z1+sbz[1])*100.f, lz2=(z2+sbz[2])*100.f, lz3=(z3+sbz[3])*100.f;

    float inv = 1.f / sqrtf(1.f + l0*l0 + l1*l1 + l2*l2);
    float dw = inv, dx = l0*inv, dy = l1*inv, dz = l2*inv;

    float s0 = d_locst[(size_t)l*4+0], s1 = d_locst[(size_t)l*4+1];
    float s2 = d_locst[(size_t)l*4+2], s3 = d_locst[(size_t)l*4+3];

    float w  = s0*dw - (s1*dx + s2*dy + s3*dz);
    float vx = s0*dx + dw*s1 + (s2*dz - s3*dy);
    float vy = s0*dy + dw*s2 + (s3*dx - s1*dz);
    float vz = s0*dz + dw*s3 + (s1*dy - s2*dx);

    int b = l / NSD, n = l - b*NSD;
    size_t base = (((size_t)b*PHS + s)*NSD + n)*4;
    if (lane < 4){
        float lv = (lane==0)?w  : (lane==1)?vx : (lane==2)?vy : vz;
        float dv = (lane==0)?dw : (lane==1)?dx : (lane==2)?dy : dz;
        float zv = (lane==0)?lz0: (lane==1)?lz1: (lane==2)?lz2: lz3;
        out[base + lane]          = lv;
        out[SEC + base + lane]    = dv;
        out[2*(size_t)SEC + base + lane] = zv;
        d_locst[(size_t)l*4 + lane] = lv;
        d_xi[(size_t)l*8 + lane]     = lv;
        d_xi[(size_t)l*8 + 4 + lane] = dv;
    }
}

// ---------------- host ----------------
extern "C" void kernel_launch(void* const* d_in, const int* in_sizes, int n_in,
                              void* d_out, int out_size){
    const float* x      = (const float*)d_in[0];
    const float* enc    = (const float*)d_in[1];
    const float* fe     = (const float*)d_in[2];
    const float* z      = (const float*)d_in[3];
    const float* G      = (const float*)d_in[5];
    const float* Gadd   = (const float*)d_in[6];
    const float* W_ih   = (const float*)d_in[7];
    const float* W_hh   = (const float*)d_in[8];
    const float* b_lstm = (const float*)d_in[9];
    const float* W_fc   = (const float*)d_in[10];
    const float* b_fc   = (const float*)d_in[11];
    const float* W_fc2  = (const float*)d_in[12];
    const float* b_fc2  = (const float*)d_in[13];
    const float* W_h1   = (const float*)d_in[14];
    const float* b_h1   = (const float*)d_in[15];
    const float* W_h2   = (const float*)d_in[16];
    const float* b_h2   = (const float*)d_in[17];
    const float* W_hd   = (const float*)d_in[18];
    const float* b_hd   = (const float*)d_in[19];
    const float* Wq     = (const float*)d_in[20];
    const float* bq     = (const float*)d_in[21];
    const float* Wk     = (const float*)d_in[22];
    const float* bk     = (const float*)d_in[23];
    const float* Wv     = (const float*)d_in[24];
    const float* bv     = (const float*)d_in[25];
    const float* Wo     = (const float*)d_in[26];
    const float* bo     = (const float*)d_in[27];
    const float* W_loc  = (const float*)d_in[28];
    const float* b_loc  = (const float*)d_in[29];
    const float* W_lz   = (const float*)d_in[30];
    const float* b_lz   = (const float*)d_in[31];
    float* out = (float*)d_out;

    float *ph0,*ph1,*pc0,*pc1,*pgeff,*pencz,*pezm,*pX,*pinp,*pym,*pyy,*pymix,*pwcat,*pwfc,*pbcat;
    cudaGetSymbolAddress((void**)&ph0,   d_h0);
    cudaGetSymbolAddress((void**)&ph1,   d_h1);
    cudaGetSymbolAddress((void**)&pc0,   d_c0);
    cudaGetSymbolAddress((void**)&pc1,   d_c1);
    cudaGetSymbolAddress((void**)&pgeff, d_Geff);
    cudaGetSymbolAddress((void**)&pencz, d_encz);
    cudaGetSymbolAddress((void**)&pezm,  d_ezm);
    cudaGetSymbolAddress((void**)&pX,    d_X);
    cudaGetSymbolAddress((void**)&pinp,  d_inp);
    cudaGetSymbolAddress((void**)&pym,   d_ym);
    cudaGetSymbolAddress((void**)&pyy,   d_yy);
    cudaGetSymbolAddress((void**)&pymix, d_ymix);
    cudaGetSymbolAddress((void**)&pwcat, d_Wcat);
    cudaGetSymbolAddress((void**)&pwfc,  d_Wfccat);
    cudaGetSymbolAddress((void**)&pbcat, d_bcat);

    // prologue
    k_prep_geff<<<1, 512>>>(G, Gadd);
    k_prep_wcat<<<(272*1024 + 255)/256, 256>>>(W_ih, W_hh);
    k_prep_fc<<<(256*128 + 255)/256, 256>>>(W_fc, b_fc, W_fc2, b_fc2);
    k_encz<<<(LL*64 + 255)/256, 256>>>(z, enc);
    k_mix<<<(BSZ*64 + 127)/128, 128>>>(G, pencz, 64, pezm, 64, 0, 0);
    k_gemm_tf32<<<dim3(2,168), 256>>>(pezm, W_h1, b_h1, ph0, 256, 64, 0);
    k_gemm_tf32<<<dim3(2,168), 256>>>(pezm, W_h2, b_h2, pc0, 256, 64, 0);
    k_kv<<<(LL*ET + 127)/128, 128>>>(fe, Wk, bk, Wv, bv);
    k_init<<<(LL*8 + 255)/256, 256>>>(x);

    for (int s = 0; s < PHS; ++s){
        float* hc = (s & 1) ? ph1 : ph0;
        float* cc = (s & 1) ? pc1 : pc0;
        float* hn = (s & 1) ? ph0 : ph1;
        float* cn = (s & 1) ? pc0 : pc1;

        k_attn<<<LL/4, 128>>>(cc, W_hd, b_hd, Wq, bq, Wo, bo);
        k_mix<<<(BSZ*16  + 127)/128, 128>>>(pgeff, pinp, 16,  pX, 272, 0,  0);
        k_mix<<<(BSZ*256 + 127)/128, 128>>>(pgeff, hc,   256, pX, 272, 16, 0);
        k_gemm_lstm<<<dim3(8,168), 256>>>(pX, pwcat, b_lstm, cc, cn, hn);
        k_mix<<<(BSZ*256 + 127)/128, 128>>>(G, hn, 256, pym, 256, 0, 1);
        k_gemm_tf32<<<dim3(1,168), 256>>>(pym, pwfc, pbcat, pyy, 128, 256, 1);
        k_mix<<<(BSZ*128 + 127)/128, 128>>>(G, pyy, 128, pymix, 128, 0, 0);
        k_final<<<LL/4, 128>>>(W_loc, b_loc, W_lz, b_lz, out, s);
    }
}